// round 10
// baseline (speedup 1.0000x reference)
#include <cuda_runtime.h>
#include <cuda_fp16.h>
#include <cstdint>
#include <math.h>

#define TOK 16384
#define HID 512
#define FF  2048
#define NE  8
#define ROWCAP (TOK*2 + NE*128)

typedef unsigned long long u64;

// ---------------- device scratch (no allocations allowed) ----------------
__device__ int   g_cnt[NE];
__device__ int   g_off[NE];
__device__ int   g_list[NE][TOK];
__device__ float g_wt[NE][TOK];

__device__ __half g_a[(size_t)ROWCAP * HID];
__device__ __half g_h[(size_t)ROWCAP * FF];
__device__ __half g_w1[(size_t)NE * FF * HID];  // [e][n(FF)][k(HID)]
__device__ __half g_w2[(size_t)NE * HID * FF];  // [e][n(HID)][k(FF)]

// ---------------- helpers ----------------
__device__ __forceinline__ uint32_t smem_u32(const void* p) {
    uint32_t a;
    asm("{ .reg .u64 t; cvta.to.shared.u64 t, %1; cvt.u32.u64 %0, t; }" : "=r"(a) : "l"(p));
    return a;
}
#define SWZ(x) ((x) ^ (((x) >> 3) & 0x70))

__device__ __forceinline__ void cp16(uint32_t dst, const void* src) {
    asm volatile("cp.async.cg.shared.global [%0], [%1], 16;" :: "r"(dst), "l"(src));
}
__device__ __forceinline__ void ldsm_x4(uint32_t& r0, uint32_t& r1, uint32_t& r2, uint32_t& r3,
                                        uint32_t addr) {
    asm volatile("ldmatrix.sync.aligned.m8n8.x4.shared.b16 {%0,%1,%2,%3}, [%4];"
                 : "=r"(r0), "=r"(r1), "=r"(r2), "=r"(r3) : "r"(addr));
}
__device__ __forceinline__ void mma16816(float* d, const uint32_t* a, uint32_t b0, uint32_t b1) {
    asm volatile("mma.sync.aligned.m16n8k16.row.col.f32.f16.f16.f32 "
                 "{%0,%1,%2,%3},{%4,%5,%6,%7},{%8,%9},{%0,%1,%2,%3};"
                 : "+f"(d[0]), "+f"(d[1]), "+f"(d[2]), "+f"(d[3])
                 : "r"(a[0]), "r"(a[1]), "r"(a[2]), "r"(a[3]), "r"(b0), "r"(b1));
}
__device__ __forceinline__ float gelu_f(float v) {
    float u = 1.5957691216057308f * (v + 0.044715f * v * v * v);
    return v / (1.0f + __expf(-u));
}
__device__ __forceinline__ uint32_t pack_h2(float a, float b) {
    __half ah = __float2half_rn(a);
    __half bh = __float2half_rn(b);
    return (uint32_t)__half_as_ushort(ah) | ((uint32_t)__half_as_ushort(bh) << 16);
}

// ---------------- kernel 0: zero counters ----------------
__global__ void zero_cnt_kernel() {
    if (threadIdx.x < NE) g_cnt[threadIdx.x] = 0;
}

// ---------------- kernel 1: gating (one warp per token, float4 ILP) ----------------
__global__ void gate_kernel(const float* __restrict__ x,
                            const float* __restrict__ Wg,
                            const float* __restrict__ bg) {
    int t = blockIdx.x * 8 + (threadIdx.x >> 5);
    int lane = threadIdx.x & 31;
    const float4* xr4 = (const float4*)(x + (size_t)t * HID);

    float acc[NE];
#pragma unroll
    for (int e = 0; e < NE; e++) acc[e] = 0.0f;

#pragma unroll
    for (int i = 0; i < 4; i++) {
        int c = i * 32 + lane;           // float4 index within row
        float4 xv = xr4[c];
        float xs[4] = {xv.x, xv.y, xv.z, xv.w};
        const float4* wg = (const float4*)(Wg + (size_t)(c * 4) * NE);
#pragma unroll
        for (int q = 0; q < 4; q++) {
            float4 w0 = wg[q * 2];
            float4 w1 = wg[q * 2 + 1];
            acc[0] += xs[q] * w0.x; acc[1] += xs[q] * w0.y;
            acc[2] += xs[q] * w0.z; acc[3] += xs[q] * w0.w;
            acc[4] += xs[q] * w1.x; acc[5] += xs[q] * w1.y;
            acc[6] += xs[q] * w1.z; acc[7] += xs[q] * w1.w;
        }
    }
#pragma unroll
    for (int off = 16; off > 0; off >>= 1) {
#pragma unroll
        for (int e = 0; e < NE; e++)
            acc[e] += __shfl_down_sync(0xffffffffu, acc[e], off);
    }
    if (lane == 0) {
        float lg[NE], p[NE];
        float m = -1e30f;
#pragma unroll
        for (int e = 0; e < NE; e++) { lg[e] = acc[e] + bg[e]; m = fmaxf(m, lg[e]); }
        float s = 0.0f;
#pragma unroll
        for (int e = 0; e < NE; e++) { p[e] = expf(lg[e] - m); s += p[e]; }
        float inv = 1.0f / s;
#pragma unroll
        for (int e = 0; e < NE; e++) p[e] *= inv;
        int i1 = 0;
#pragma unroll
        for (int e = 1; e < NE; e++) if (p[e] > p[i1]) i1 = e;
        int i2 = (i1 == 0) ? 1 : 0;
#pragma unroll
        for (int e = 0; e < NE; e++) if (e != i1 && p[e] > p[i2]) i2 = e;

        int pos = atomicAdd(&g_cnt[i1], 1);
        g_list[i1][pos] = t * 2 + 0;
        g_wt[i1][pos]   = p[i1];
        pos = atomicAdd(&g_cnt[i2], 1);
        g_list[i2][pos] = t * 2 + 1;
        g_wt[i2][pos]   = p[i2];
    }
}

// ---------------- kernel 2: padded prefix offsets ----------------
__global__ void offs_kernel() {
    if (threadIdx.x == 0) {
        int o = 0;
#pragma unroll
        for (int e = 0; e < NE; e++) { g_off[e] = o; o += (g_cnt[e] + 127) & ~127; }
    }
}

// ---------------- kernel 3: pack A rows (flat over padded rows) ----------------
__global__ void __launch_bounds__(256)
pack_a_kernel(const float* __restrict__ x) {
    int row = blockIdx.x * 2 + (threadIdx.x >> 7);
    int t4  = threadIdx.x & 127;
    if (row >= ROWCAP) return;

    int e = 0;
#pragma unroll
    for (int i = 1; i < NE; i++) if (row >= g_off[i]) e = i;
    int m = row - g_off[e];

    float4 v = make_float4(0.f, 0.f, 0.f, 0.f);
    if (m < g_cnt[e]) {
        int token = g_list[e][m] >> 1;
        v = *(const float4*)(x + (size_t)token * HID + t4 * 4);
    }
    *(uint2*)(g_a + (size_t)row * HID + t4 * 4) =
        make_uint2(pack_h2(v.x, v.y), pack_h2(v.z, v.w));
}

// ---------------- kernel 4: weight transpose -> fp16 [N][K] (128k x 32n tiles) ----------------
template <int K, int N>
__device__ __forceinline__ void conv_w_body(const float* __restrict__ W,
                                            __half* __restrict__ oh) {
    __shared__ __half st[32][136];
    const int e  = blockIdx.z;
    const int n0 = blockIdx.x * 32;
    const int k0 = blockIdx.y * 128;
    const float* Wp = W + (size_t)e * K * N + (size_t)k0 * N + n0;

#pragma unroll
    for (int i = 0; i < 4; i++) {
        int idx = threadIdx.x + i * 256;      // 0..1023
        int row = idx >> 3;                   // k within tile 0..127
        int c4  = idx & 7;                    // float4 col 0..7
        float4 v = *(const float4*)(Wp + (size_t)row * N + c4 * 4);
        int n = c4 * 4;
        st[n + 0][row] = __float2half_rn(v.x);
        st[n + 1][row] = __float2half_rn(v.y);
        st[n + 2][row] = __float2half_rn(v.z);
        st[n + 3][row] = __float2half_rn(v.w);
    }
    __syncthreads();

    __half* op = oh + (size_t)e * N * K + (size_t)n0 * K + k0;
    // 32 n-rows x 128 k halves = 2048 uint32 stores; 256 threads x 8 iters
#pragma unroll
    for (int i = 0; i < 8; i++) {
        int idx = threadIdx.x + i * 256;      // 0..2047
        int n = idx >> 6;                     // 0..31
        int j = idx & 63;                     // uint32 index within 128 halves
        *(uint32_t*)(op + (size_t)n * K + j * 2) = *(uint32_t*)&st[n][j * 2];
    }
}
__global__ void __launch_bounds__(256) conv_w1_kernel(const float* __restrict__ W) {
    conv_w_body<HID, FF>(W, g_w1);
}
__global__ void __launch_bounds__(256) conv_w2_kernel(const float* __restrict__ W) {
    conv_w_body<FF, HID>(W, g_w2);
}

// ---------------- HMMA mainloop: 128x128 CTA tile, K-tile 64, single fp16 pass ----------------
// KLEN = length of K to process; STRIDE = row stride of A and B in elements.
template <int KLEN, int STRIDE>
__device__ __forceinline__ void mma_loop(
    const __half* __restrict__ A, const __half* __restrict__ B,
    uint32_t sm, float acc[2][8][4])
{
    const uint32_t smA = sm;
    const uint32_t smB = sm + 49152;

    const int tid  = threadIdx.x;
    const int w    = tid >> 5, lane = tid & 31;
    const int wm   = (w & 3) * 32, wn = (w >> 2) * 64;
    const int lr   = tid >> 1;
    const int lc   = (tid & 1) * 4;
    const int lrow = lane & 15;
    const int lkof = (lane >> 4) * 8;

    uint32_t st_off[4];
#pragma unroll
    for (int i = 0; i < 4; i++) st_off[i] = SWZ(lr * 128 + (lc + i) * 16);

    constexpr int nT = KLEN / 64;
    const size_t lbase = (size_t)lr * STRIDE + lc * 8;

#pragma unroll
    for (int s = 0; s < 2; s++) {
        const __half* ap = A + lbase + s * 64;
        const __half* bp = B + lbase + s * 64;
        uint32_t ab = smA + s * 16384, bb = smB + s * 16384;
#pragma unroll
        for (int i = 0; i < 4; i++) {
            cp16(ab + st_off[i], ap + i * 8);
            cp16(bb + st_off[i], bp + i * 8);
        }
        asm volatile("cp.async.commit_group;" ::: "memory");
    }

    int buf = 0, buf2 = 2;
    for (int t = 0; t < nT; t++) {
        asm volatile("cp.async.wait_group 1;" ::: "memory");
        __syncthreads();

        int tn = t + 2;
        if (tn < nT) {
            const __half* ap = A + lbase + tn * 64;
            const __half* bp = B + lbase + tn * 64;
            uint32_t ab = smA + buf2 * 16384, bb = smB + buf2 * 16384;
#pragma unroll
            for (int i = 0; i < 4; i++) {
                cp16(ab + st_off[i], ap + i * 8);
                cp16(bb + st_off[i], bp + i * 8);
            }
        }
        asm volatile("cp.async.commit_group;" ::: "memory");

        uint32_t ab = smA + buf * 16384, bb = smB + buf * 16384;
#pragma unroll
        for (int kk = 0; kk < 4; kk++) {
            const int kb = (kk * 16 + lkof) * 2;
            uint32_t a0[4], a1[4], B0[4], B1[4], B2[4], B3[4];
            ldsm_x4(a0[0], a0[1], a0[2], a0[3], ab + SWZ((wm + lrow) * 128 + kb));
            ldsm_x4(a1[0], a1[1], a1[2], a1[3], ab + SWZ((wm + 16 + lrow) * 128 + kb));
            ldsm_x4(B0[0], B0[1], B0[2], B0[3], bb + SWZ((wn + lrow) * 128 + kb));
            ldsm_x4(B1[0], B1[1], B1[2], B1[3], bb + SWZ((wn + 16 + lrow) * 128 + kb));
            ldsm_x4(B2[0], B2[1], B2[2], B2[3], bb + SWZ((wn + 32 + lrow) * 128 + kb));
            ldsm_x4(B3[0], B3[1], B3[2], B3[3], bb + SWZ((wn + 48 + lrow) * 128 + kb));

            mma16816(acc[0][0], a0, B0[0], B0[2]);
            mma16816(acc[1][0], a1, B0[0], B0[2]);
            mma16816(acc[0][1], a0, B0[1], B0[3]);
            mma16816(acc[1][1], a1, B0[1], B0[3]);
            mma16816(acc[0][2], a0, B1[0], B1[2]);
            mma16816(acc[1][2], a1, B1[0], B1[2]);
            mma16816(acc[0][3], a0, B1[1], B1[3]);
            mma16816(acc[1][3], a1, B1[1], B1[3]);
            mma16816(acc[0][4], a0, B2[0], B2[2]);
            mma16816(acc[1][4], a1, B2[0], B2[2]);
            mma16816(acc[0][5], a0, B2[1], B2[3]);
            mma16816(acc[1][5], a1, B2[1], B2[3]);
            mma16816(acc[0][6], a0, B3[0], B3[2]);
            mma16816(acc[1][6], a1, B3[0], B3[2]);
            mma16816(acc[0][7], a0, B3[1], B3[3]);
            mma16816(acc[1][7], a1, B3[1], B3[3]);
        }
        buf  = (buf == 2) ? 0 : buf + 1;
        buf2 = (buf2 == 2) ? 0 : buf2 + 1;
    }
}

#define SMEM_DYN 98304

// ---------------- kernel 5: grouped GEMM1  h = gelu(x @ W1[e] + b1[e]) ----------------
__global__ void __launch_bounds__(256, 2)
gemm1_mma(const float* __restrict__ b1) {
    const int e   = blockIdx.z;
    const int cnt = g_cnt[e];
    const int m0  = blockIdx.y * 128;
    if (m0 >= cnt) return;
    const int n0  = blockIdx.x * 128;
    const size_t row0 = (size_t)g_off[e] + m0;

    extern __shared__ char dynsm[];
    uint32_t sm = smem_u32(dynsm);

    float acc[2][8][4];
#pragma unroll
    for (int i = 0; i < 2; i++)
#pragma unroll
        for (int j = 0; j < 8; j++)
#pragma unroll
            for (int q = 0; q < 4; q++) acc[i][j][q] = 0.0f;

    mma_loop<HID, HID>(g_a + row0 * HID,
                       g_w1 + ((size_t)e * FF + n0) * HID,
                       sm, acc);

    const int w = threadIdx.x >> 5, lane = threadIdx.x & 31;
    const int wm = (w & 3) * 32, wn = (w >> 2) * 64;
    const float* bias = b1 + (size_t)e * FF + n0;
#pragma unroll
    for (int mi = 0; mi < 2; mi++) {
#pragma unroll
        for (int half = 0; half < 2; half++) {
            int rl = wm + mi * 16 + (lane >> 2) + half * 8;
            size_t hb = (row0 + rl) * FF + n0;
#pragma unroll
            for (int j = 0; j < 8; j++) {
                int c = wn + j * 8 + (lane & 3) * 2;
                float d0 = acc[mi][j][half * 2 + 0] + bias[c];
                float d1 = acc[mi][j][half * 2 + 1] + bias[c + 1];
                *(uint32_t*)(g_h + hb + c) = pack_h2(gelu_f(d0), gelu_f(d1));
            }
        }
    }
}

// ---------------- kernel 6: grouped GEMM2 (K-split 2)  out += wgt*(h @ W2[e] + b2[e]) ----------------
__global__ void __launch_bounds__(256, 2)
gemm2_mma(const float* __restrict__ b2, float* __restrict__ out) {
    const int ez  = blockIdx.z;
    const int e   = ez >> 1;
    const int ks  = ez & 1;            // K-split index
    const int cnt = g_cnt[e];
    const int m0  = blockIdx.y * 128;
    if (m0 >= cnt) return;
    const int n0  = blockIdx.x * 128;
    const size_t row0 = (size_t)g_off[e] + m0;
    const int koff = ks * (FF / 2);

    extern __shared__ char dynsm[];
    uint32_t sm = smem_u32(dynsm);

    float acc[2][8][4];
#pragma unroll
    for (int i = 0; i < 2; i++)
#pragma unroll
        for (int j = 0; j < 8; j++)
#pragma unroll
            for (int q = 0; q < 4; q++) acc[i][j][q] = 0.0f;

    mma_loop<FF / 2, FF>(g_h + row0 * FF + koff,
                         g_w2 + ((size_t)e * HID + n0) * FF + koff,
                         sm, acc);

    const int w = threadIdx.x >> 5, lane = threadIdx.x & 31;
    const int wm = (w & 3) * 32, wn = (w >> 2) * 64;
    const float* bias = b2 + (size_t)e * HID + n0;
    const float bsc = (ks == 0) ? 1.0f : 0.0f;
#pragma unroll
    for (int mi = 0; mi < 2; mi++) {
#pragma unroll
        for (int half = 0; half < 2; half++) {
            int m = m0 + wm + mi * 16 + (lane >> 2) + half * 8;
            if (m >= cnt) continue;
            int token = g_list[e][m] >> 1;
            float wgt = g_wt[e][m];
            float* orow = out + (size_t)token * HID + n0;
#pragma unroll
            for (int j = 0; j < 8; j++) {
                int c = wn + j * 8 + (lane & 3) * 2;
                atomicAdd(orow + c,     wgt * (acc[mi][j][half * 2 + 0] + bsc * bias[c]));
                atomicAdd(orow + c + 1, wgt * (acc[mi][j][half * 2 + 1] + bsc * bias[c + 1]));
            }
        }
    }
}

// ---------------- host launcher ----------------
extern "C" void kernel_launch(void* const* d_in, const int* in_sizes, int n_in,
                              void* d_out, int out_size) {
    const float* x  = (const float*)d_in[0];
    const float* Wg = (const float*)d_in[1];
    const float* bg = (const float*)d_in[2];
    const float* W1 = (const float*)d_in[3];
    const float* b1 = (const float*)d_in[4];
    const float* W2 = (const float*)d_in[5];
    const float* b2 = (const float*)d_in[6];
    float* out = (float*)d_out;

    cudaFuncSetAttribute(gemm1_mma, cudaFuncAttributeMaxDynamicSharedMemorySize, SMEM_DYN);
    cudaFuncSetAttribute(gemm2_mma, cudaFuncAttributeMaxDynamicSharedMemorySize, SMEM_DYN);

    cudaMemsetAsync(out, 0, (size_t)out_size * sizeof(float));
    zero_cnt_kernel<<<1, 32>>>();
    gate_kernel<<<TOK / 8, 256>>>(x, Wg, bg);
    offs_kernel<<<1, 32>>>();
    pack_a_kernel<<<(ROWCAP + 1) / 2, 256>>>(x);
    conv_w1_kernel<<<dim3(FF / 32, HID / 128, NE), 256>>>(W1);
    conv_w2_kernel<<<dim3(HID / 32, FF / 128, NE), 256>>>(W2);
    gemm1_mma<<<dim3(FF / 128, TOK / 128, NE), 256, SMEM_DYN>>>(b1);
    gemm2_mma<<<dim3(HID / 128, TOK / 128, NE * 2), 256, SMEM_DYN>>>(b2, out);
}

// round 11
// speedup vs baseline: 1.0279x; 1.0279x over previous
#include <cuda_runtime.h>
#include <cuda_fp16.h>
#include <cstdint>
#include <math.h>

#define TOK 16384
#define HID 512
#define FF  2048
#define NE  8
#define ROWCAP (TOK*2 + NE*128)

typedef unsigned long long u64;

// ---------------- device scratch (no allocations allowed) ----------------
__device__ int   g_cnt[NE];
__device__ int   g_off[NE];
__device__ int   g_list[NE][TOK];
__device__ float g_wt[NE][TOK];

__device__ __half g_a[(size_t)ROWCAP * HID];
__device__ __half g_h[(size_t)ROWCAP * FF];
__device__ __half g_w1[(size_t)NE * FF * HID];  // [e][n(FF)][k(HID)]
__device__ __half g_w2[(size_t)NE * HID * FF];  // [e][n(HID)][k(FF)]

// ---------------- helpers ----------------
__device__ __forceinline__ uint32_t smem_u32(const void* p) {
    uint32_t a;
    asm("{ .reg .u64 t; cvta.to.shared.u64 t, %1; cvt.u32.u64 %0, t; }" : "=r"(a) : "l"(p));
    return a;
}
#define SWZ(x) ((x) ^ (((x) >> 3) & 0x70))

__device__ __forceinline__ void cp16(uint32_t dst, const void* src) {
    asm volatile("cp.async.cg.shared.global [%0], [%1], 16;" :: "r"(dst), "l"(src));
}
__device__ __forceinline__ void ldsm_x4(uint32_t& r0, uint32_t& r1, uint32_t& r2, uint32_t& r3,
                                        uint32_t addr) {
    asm volatile("ldmatrix.sync.aligned.m8n8.x4.shared.b16 {%0,%1,%2,%3}, [%4];"
                 : "=r"(r0), "=r"(r1), "=r"(r2), "=r"(r3) : "r"(addr));
}
__device__ __forceinline__ void mma16816(float* d, const uint32_t* a, uint32_t b0, uint32_t b1) {
    asm volatile("mma.sync.aligned.m16n8k16.row.col.f32.f16.f16.f32 "
                 "{%0,%1,%2,%3},{%4,%5,%6,%7},{%8,%9},{%0,%1,%2,%3};"
                 : "+f"(d[0]), "+f"(d[1]), "+f"(d[2]), "+f"(d[3])
                 : "r"(a[0]), "r"(a[1]), "r"(a[2]), "r"(a[3]), "r"(b0), "r"(b1));
}
__device__ __forceinline__ float gelu_f(float v) {
    float u = 1.5957691216057308f * (v + 0.044715f * v * v * v);
    return v / (1.0f + __expf(-u));
}
__device__ __forceinline__ uint32_t pack_h2(float a, float b) {
    __half ah = __float2half_rn(a);
    __half bh = __float2half_rn(b);
    return (uint32_t)__half_as_ushort(ah) | ((uint32_t)__half_as_ushort(bh) << 16);
}

// ---------------- kernel 0: zero counters ----------------
__global__ void zero_cnt_kernel() {
    if (threadIdx.x < NE) g_cnt[threadIdx.x] = 0;
}

// ---------------- kernel 1: gating (one warp per token, float4 ILP) ----------------
__global__ void gate_kernel(const float* __restrict__ x,
                            const float* __restrict__ Wg,
                            const float* __restrict__ bg) {
    int t = blockIdx.x * 8 + (threadIdx.x >> 5);
    int lane = threadIdx.x & 31;
    const float4* xr4 = (const float4*)(x + (size_t)t * HID);

    float acc[NE];
#pragma unroll
    for (int e = 0; e < NE; e++) acc[e] = 0.0f;

#pragma unroll
    for (int i = 0; i < 4; i++) {
        int c = i * 32 + lane;
        float4 xv = xr4[c];
        float xs[4] = {xv.x, xv.y, xv.z, xv.w};
        const float4* wg = (const float4*)(Wg + (size_t)(c * 4) * NE);
#pragma unroll
        for (int q = 0; q < 4; q++) {
            float4 w0 = wg[q * 2];
            float4 w1 = wg[q * 2 + 1];
            acc[0] += xs[q] * w0.x; acc[1] += xs[q] * w0.y;
            acc[2] += xs[q] * w0.z; acc[3] += xs[q] * w0.w;
            acc[4] += xs[q] * w1.x; acc[5] += xs[q] * w1.y;
            acc[6] += xs[q] * w1.z; acc[7] += xs[q] * w1.w;
        }
    }
#pragma unroll
    for (int off = 16; off > 0; off >>= 1) {
#pragma unroll
        for (int e = 0; e < NE; e++)
            acc[e] += __shfl_down_sync(0xffffffffu, acc[e], off);
    }
    if (lane == 0) {
        float lg[NE], p[NE];
        float m = -1e30f;
#pragma unroll
        for (int e = 0; e < NE; e++) { lg[e] = acc[e] + bg[e]; m = fmaxf(m, lg[e]); }
        float s = 0.0f;
#pragma unroll
        for (int e = 0; e < NE; e++) { p[e] = expf(lg[e] - m); s += p[e]; }
        float inv = 1.0f / s;
#pragma unroll
        for (int e = 0; e < NE; e++) p[e] *= inv;
        int i1 = 0;
#pragma unroll
        for (int e = 1; e < NE; e++) if (p[e] > p[i1]) i1 = e;
        int i2 = (i1 == 0) ? 1 : 0;
#pragma unroll
        for (int e = 0; e < NE; e++) if (e != i1 && p[e] > p[i2]) i2 = e;

        int pos = atomicAdd(&g_cnt[i1], 1);
        g_list[i1][pos] = t * 2 + 0;
        g_wt[i1][pos]   = p[i1];
        pos = atomicAdd(&g_cnt[i2], 1);
        g_list[i2][pos] = t * 2 + 1;
        g_wt[i2][pos]   = p[i2];
    }
}

// ---------------- kernel 2: padded prefix offsets ----------------
__global__ void offs_kernel() {
    if (threadIdx.x == 0) {
        int o = 0;
#pragma unroll
        for (int e = 0; e < NE; e++) { g_off[e] = o; o += (g_cnt[e] + 127) & ~127; }
    }
}

// ---------------- kernel 3: pack A rows (flat over padded rows) ----------------
__global__ void __launch_bounds__(256)
pack_a_kernel(const float* __restrict__ x) {
    int row = blockIdx.x * 2 + (threadIdx.x >> 7);
    int t4  = threadIdx.x & 127;
    if (row >= ROWCAP) return;

    int e = 0;
#pragma unroll
    for (int i = 1; i < NE; i++) if (row >= g_off[i]) e = i;
    int m = row - g_off[e];

    float4 v = make_float4(0.f, 0.f, 0.f, 0.f);
    if (m < g_cnt[e]) {
        int token = g_list[e][m] >> 1;
        v = *(const float4*)(x + (size_t)token * HID + t4 * 4);
    }
    *(uint2*)(g_a + (size_t)row * HID + t4 * 4) =
        make_uint2(pack_h2(v.x, v.y), pack_h2(v.z, v.w));
}

// ---------------- kernel 4: weight transpose -> fp16 [N][K] (128k x 32n tiles) ----------------
template <int K, int N>
__device__ __forceinline__ void conv_w_body(const float* __restrict__ W,
                                            __half* __restrict__ oh) {
    __shared__ __half st[32][136];
    const int e  = blockIdx.z;
    const int n0 = blockIdx.x * 32;
    const int k0 = blockIdx.y * 128;
    const float* Wp = W + (size_t)e * K * N + (size_t)k0 * N + n0;

#pragma unroll
    for (int i = 0; i < 4; i++) {
        int idx = threadIdx.x + i * 256;
        int row = idx >> 3;
        int c4  = idx & 7;
        float4 v = *(const float4*)(Wp + (size_t)row * N + c4 * 4);
        int n = c4 * 4;
        st[n + 0][row] = __float2half_rn(v.x);
        st[n + 1][row] = __float2half_rn(v.y);
        st[n + 2][row] = __float2half_rn(v.z);
        st[n + 3][row] = __float2half_rn(v.w);
    }
    __syncthreads();

    __half* op = oh + (size_t)e * N * K + (size_t)n0 * K + k0;
#pragma unroll
    for (int i = 0; i < 8; i++) {
        int idx = threadIdx.x + i * 256;
        int n = idx >> 6;
        int j = idx & 63;
        *(uint32_t*)(op + (size_t)n * K + j * 2) = *(uint32_t*)&st[n][j * 2];
    }
}
__global__ void __launch_bounds__(256) conv_w1_kernel(const float* __restrict__ W) {
    conv_w_body<HID, FF>(W, g_w1);
}
__global__ void __launch_bounds__(256) conv_w2_kernel(const float* __restrict__ W) {
    conv_w_body<FF, HID>(W, g_w2);
}

// ---------------- HMMA mainloop: 128x128 CTA tile, K-tile 64, single fp16 pass ----------------
template <int KLEN, int STRIDE>
__device__ __forceinline__ void mma_loop(
    const __half* __restrict__ A, const __half* __restrict__ B,
    uint32_t sm, float acc[2][8][4])
{
    const uint32_t smA = sm;
    const uint32_t smB = sm + 49152;

    const int tid  = threadIdx.x;
    const int w    = tid >> 5, lane = tid & 31;
    const int wm   = (w & 3) * 32, wn = (w >> 2) * 64;
    const int lr   = tid >> 1;
    const int lc   = (tid & 1) * 4;
    const int lrow = lane & 15;
    const int lkof = (lane >> 4) * 8;

    uint32_t st_off[4];
#pragma unroll
    for (int i = 0; i < 4; i++) st_off[i] = SWZ(lr * 128 + (lc + i) * 16);

    constexpr int nT = KLEN / 64;
    const size_t lbase = (size_t)lr * STRIDE + lc * 8;

#pragma unroll
    for (int s = 0; s < 2; s++) {
        const __half* ap = A + lbase + s * 64;
        const __half* bp = B + lbase + s * 64;
        uint32_t ab = smA + s * 16384, bb = smB + s * 16384;
#pragma unroll
        for (int i = 0; i < 4; i++) {
            cp16(ab + st_off[i], ap + i * 8);
            cp16(bb + st_off[i], bp + i * 8);
        }
        asm volatile("cp.async.commit_group;" ::: "memory");
    }

    int buf = 0, buf2 = 2;
    for (int t = 0; t < nT; t++) {
        asm volatile("cp.async.wait_group 1;" ::: "memory");
        __syncthreads();

        int tn = t + 2;
        if (tn < nT) {
            const __half* ap = A + lbase + tn * 64;
            const __half* bp = B + lbase + tn * 64;
            uint32_t ab = smA + buf2 * 16384, bb = smB + buf2 * 16384;
#pragma unroll
            for (int i = 0; i < 4; i++) {
                cp16(ab + st_off[i], ap + i * 8);
                cp16(bb + st_off[i], bp + i * 8);
            }
        }
        asm volatile("cp.async.commit_group;" ::: "memory");

        uint32_t ab = smA + buf * 16384, bb = smB + buf * 16384;
#pragma unroll
        for (int kk = 0; kk < 4; kk++) {
            const int kb = (kk * 16 + lkof) * 2;
            uint32_t a0[4], a1[4], B0[4], B1[4], B2[4], B3[4];
            ldsm_x4(a0[0], a0[1], a0[2], a0[3], ab + SWZ((wm + lrow) * 128 + kb));
            ldsm_x4(a1[0], a1[1], a1[2], a1[3], ab + SWZ((wm + 16 + lrow) * 128 + kb));
            ldsm_x4(B0[0], B0[1], B0[2], B0[3], bb + SWZ((wn + lrow) * 128 + kb));
            ldsm_x4(B1[0], B1[1], B1[2], B1[3], bb + SWZ((wn + 16 + lrow) * 128 + kb));
            ldsm_x4(B2[0], B2[1], B2[2], B2[3], bb + SWZ((wn + 32 + lrow) * 128 + kb));
            ldsm_x4(B3[0], B3[1], B3[2], B3[3], bb + SWZ((wn + 48 + lrow) * 128 + kb));

            mma16816(acc[0][0], a0, B0[0], B0[2]);
            mma16816(acc[1][0], a1, B0[0], B0[2]);
            mma16816(acc[0][1], a0, B0[1], B0[3]);
            mma16816(acc[1][1], a1, B0[1], B0[3]);
            mma16816(acc[0][2], a0, B1[0], B1[2]);
            mma16816(acc[1][2], a1, B1[0], B1[2]);
            mma16816(acc[0][3], a0, B1[1], B1[3]);
            mma16816(acc[1][3], a1, B1[1], B1[3]);
            mma16816(acc[0][4], a0, B2[0], B2[2]);
            mma16816(acc[1][4], a1, B2[0], B2[2]);
            mma16816(acc[0][5], a0, B2[1], B2[3]);
            mma16816(acc[1][5], a1, B2[1], B2[3]);
            mma16816(acc[0][6], a0, B3[0], B3[2]);
            mma16816(acc[1][6], a1, B3[0], B3[2]);
            mma16816(acc[0][7], a0, B3[1], B3[3]);
            mma16816(acc[1][7], a1, B3[1], B3[3]);
        }
        buf  = (buf == 2) ? 0 : buf + 1;
        buf2 = (buf2 == 2) ? 0 : buf2 + 1;
    }
}

#define SMEM_DYN 98304

// ---------------- kernel 5: grouped GEMM1  h = gelu(x @ W1[e] + b1[e]) ----------------
__global__ void __launch_bounds__(256, 2)
gemm1_mma(const float* __restrict__ b1) {
    const int e   = blockIdx.z;
    const int cnt = g_cnt[e];
    const int m0  = blockIdx.y * 128;
    if (m0 >= cnt) return;
    const int n0  = blockIdx.x * 128;
    const size_t row0 = (size_t)g_off[e] + m0;

    extern __shared__ char dynsm[];
    uint32_t sm = smem_u32(dynsm);

    float acc[2][8][4];
#pragma unroll
    for (int i = 0; i < 2; i++)
#pragma unroll
        for (int j = 0; j < 8; j++)
#pragma unroll
            for (int q = 0; q < 4; q++) acc[i][j][q] = 0.0f;

    mma_loop<HID, HID>(g_a + row0 * HID,
                       g_w1 + ((size_t)e * FF + n0) * HID,
                       sm, acc);

    const int w = threadIdx.x >> 5, lane = threadIdx.x & 31;
    const int wm = (w & 3) * 32, wn = (w >> 2) * 64;
    const float* bias = b1 + (size_t)e * FF + n0;
#pragma unroll
    for (int mi = 0; mi < 2; mi++) {
#pragma unroll
        for (int half = 0; half < 2; half++) {
            int rl = wm + mi * 16 + (lane >> 2) + half * 8;
            size_t hb = (row0 + rl) * FF + n0;
#pragma unroll
            for (int j = 0; j < 8; j++) {
                int c = wn + j * 8 + (lane & 3) * 2;
                float d0 = acc[mi][j][half * 2 + 0] + bias[c];
                float d1 = acc[mi][j][half * 2 + 1] + bias[c + 1];
                *(uint32_t*)(g_h + hb + c) = pack_h2(gelu_f(d0), gelu_f(d1));
            }
        }
    }
}

// ---------------- kernel 6: grouped GEMM2  out += wgt*(h @ W2[e] + b2[e]) ----------------
__global__ void __launch_bounds__(256, 2)
gemm2_mma(const float* __restrict__ b2, float* __restrict__ out) {
    const int e   = blockIdx.z;
    const int cnt = g_cnt[e];
    const int m0  = blockIdx.y * 128;
    if (m0 >= cnt) return;
    const int n0  = blockIdx.x * 128;
    const size_t row0 = (size_t)g_off[e] + m0;

    extern __shared__ char dynsm[];
    uint32_t sm = smem_u32(dynsm);

    float acc[2][8][4];
#pragma unroll
    for (int i = 0; i < 2; i++)
#pragma unroll
        for (int j = 0; j < 8; j++)
#pragma unroll
            for (int q = 0; q < 4; q++) acc[i][j][q] = 0.0f;

    mma_loop<FF, FF>(g_h + row0 * FF,
                     g_w2 + ((size_t)e * HID + n0) * FF,
                     sm, acc);

    const int w = threadIdx.x >> 5, lane = threadIdx.x & 31;
    const int wm = (w & 3) * 32, wn = (w >> 2) * 64;
    const float* bias = b2 + (size_t)e * HID + n0;
#pragma unroll
    for (int mi = 0; mi < 2; mi++) {
#pragma unroll
        for (int half = 0; half < 2; half++) {
            int m = m0 + wm + mi * 16 + (lane >> 2) + half * 8;
            if (m >= cnt) continue;
            int token = g_list[e][m] >> 1;
            float wgt = g_wt[e][m];
            float* orow = out + (size_t)token * HID + n0;
#pragma unroll
            for (int j = 0; j < 8; j++) {
                int c = wn + j * 8 + (lane & 3) * 2;
                atomicAdd(orow + c,     wgt * (acc[mi][j][half * 2 + 0] + bias[c]));
                atomicAdd(orow + c + 1, wgt * (acc[mi][j][half * 2 + 1] + bias[c + 1]));
            }
        }
    }
}

// ---------------- host launcher ----------------
extern "C" void kernel_launch(void* const* d_in, const int* in_sizes, int n_in,
                              void* d_out, int out_size) {
    const float* x  = (const float*)d_in[0];
    const float* Wg = (const float*)d_in[1];
    const float* bg = (const float*)d_in[2];
    const float* W1 = (const float*)d_in[3];
    const float* b1 = (const float*)d_in[4];
    const float* W2 = (const float*)d_in[5];
    const float* b2 = (const float*)d_in[6];
    float* out = (float*)d_out;

    cudaFuncSetAttribute(gemm1_mma, cudaFuncAttributeMaxDynamicSharedMemorySize, SMEM_DYN);
    cudaFuncSetAttribute(gemm2_mma, cudaFuncAttributeMaxDynamicSharedMemorySize, SMEM_DYN);

    cudaMemsetAsync(out, 0, (size_t)out_size * sizeof(float));
    zero_cnt_kernel<<<1, 32>>>();
    gate_kernel<<<TOK / 8, 256>>>(x, Wg, bg);
    offs_kernel<<<1, 32>>>();
    pack_a_kernel<<<(ROWCAP + 1) / 2, 256>>>(x);
    conv_w1_kernel<<<dim3(FF / 32, HID / 128, NE), 256>>>(W1);
    conv_w2_kernel<<<dim3(HID / 32, FF / 128, NE), 256>>>(W2);
    gemm1_mma<<<dim3(FF / 128, TOK / 128, NE), 256, SMEM_DYN>>>(b1);
    gemm2_mma<<<dim3(HID / 128, TOK / 128, NE), 256, SMEM_DYN>>>(b2, out);
}

// round 12
// speedup vs baseline: 1.0655x; 1.0366x over previous
#include <cuda_runtime.h>
#include <cuda_fp16.h>
#include <cstdint>
#include <math.h>

#define TOK 16384
#define HID 512
#define FF  2048
#define NE  8

typedef unsigned long long u64;

// ---------------- device scratch (no allocations allowed) ----------------
__device__ int   g_cnt[NE];
__device__ int   g_list[NE][TOK];
__device__ float g_wt[NE][TOK];

__device__ __half g_a2[(size_t)NE * TOK * HID];  // per-expert gathered A rows (fp16)
__device__ __half g_h[(size_t)NE * TOK * FF];    // per-expert intermediate (fp16)
__device__ __half g_w1[(size_t)NE * FF * HID];   // [e][n(FF)][k(HID)]
__device__ __half g_w2[(size_t)NE * HID * FF];   // [e][n(HID)][k(FF)]

// ---------------- helpers ----------------
__device__ __forceinline__ uint32_t smem_u32(const void* p) {
    uint32_t a;
    asm("{ .reg .u64 t; cvta.to.shared.u64 t, %1; cvt.u32.u64 %0, t; }" : "=r"(a) : "l"(p));
    return a;
}
#define SWZ(x) ((x) ^ (((x) >> 3) & 0x70))

__device__ __forceinline__ void cp16(uint32_t dst, const void* src) {
    asm volatile("cp.async.cg.shared.global [%0], [%1], 16;" :: "r"(dst), "l"(src));
}
__device__ __forceinline__ void ldsm_x4(uint32_t& r0, uint32_t& r1, uint32_t& r2, uint32_t& r3,
                                        uint32_t addr) {
    asm volatile("ldmatrix.sync.aligned.m8n8.x4.shared.b16 {%0,%1,%2,%3}, [%4];"
                 : "=r"(r0), "=r"(r1), "=r"(r2), "=r"(r3) : "r"(addr));
}
__device__ __forceinline__ void mma16816(float* d, const uint32_t* a, uint32_t b0, uint32_t b1) {
    asm volatile("mma.sync.aligned.m16n8k16.row.col.f32.f16.f16.f32 "
                 "{%0,%1,%2,%3},{%4,%5,%6,%7},{%8,%9},{%0,%1,%2,%3};"
                 : "+f"(d[0]), "+f"(d[1]), "+f"(d[2]), "+f"(d[3])
                 : "r"(a[0]), "r"(a[1]), "r"(a[2]), "r"(a[3]), "r"(b0), "r"(b1));
}
__device__ __forceinline__ void red2(float* addr, float a, float b) {
    asm volatile("red.global.add.v2.f32 [%0], {%1, %2};" :: "l"(addr), "f"(a), "f"(b) : "memory");
}
__device__ __forceinline__ float gelu_f(float v) {
    float u = 1.5957691216057308f * (v + 0.044715f * v * v * v);
    return v / (1.0f + __expf(-u));
}
__device__ __forceinline__ uint32_t pack_h2(float a, float b) {
    __half ah = __float2half_rn(a);
    __half bh = __float2half_rn(b);
    return (uint32_t)__half_as_ushort(ah) | ((uint32_t)__half_as_ushort(bh) << 16);
}

// ---------------- kernel 0: zero counters ----------------
__global__ void zero_cnt_kernel() {
    if (threadIdx.x < NE) g_cnt[threadIdx.x] = 0;
}

// ---------------- kernel 1: gating + direct fp16 row scatter ----------------
__global__ void gate_kernel(const float* __restrict__ x,
                            const float* __restrict__ Wg,
                            const float* __restrict__ bg) {
    int t = blockIdx.x * 8 + (threadIdx.x >> 5);
    int lane = threadIdx.x & 31;
    const float4* xr4 = (const float4*)(x + (size_t)t * HID);

    float4 xs4[4];
    float acc[NE];
#pragma unroll
    for (int e = 0; e < NE; e++) acc[e] = 0.0f;

#pragma unroll
    for (int i = 0; i < 4; i++) {
        int c = i * 32 + lane;
        float4 xv = xr4[c];
        xs4[i] = xv;
        float xs[4] = {xv.x, xv.y, xv.z, xv.w};
        const float4* wg = (const float4*)(Wg + (size_t)(c * 4) * NE);
#pragma unroll
        for (int q = 0; q < 4; q++) {
            float4 w0 = wg[q * 2];
            float4 w1 = wg[q * 2 + 1];
            acc[0] += xs[q] * w0.x; acc[1] += xs[q] * w0.y;
            acc[2] += xs[q] * w0.z; acc[3] += xs[q] * w0.w;
            acc[4] += xs[q] * w1.x; acc[5] += xs[q] * w1.y;
            acc[6] += xs[q] * w1.z; acc[7] += xs[q] * w1.w;
        }
    }
#pragma unroll
    for (int off = 16; off > 0; off >>= 1) {
#pragma unroll
        for (int e = 0; e < NE; e++)
            acc[e] += __shfl_down_sync(0xffffffffu, acc[e], off);
    }

    int i1 = 0, i2 = 0, p1 = 0, p2 = 0;
    if (lane == 0) {
        float lg[NE], p[NE];
        float m = -1e30f;
#pragma unroll
        for (int e = 0; e < NE; e++) { lg[e] = acc[e] + bg[e]; m = fmaxf(m, lg[e]); }
        float s = 0.0f;
#pragma unroll
        for (int e = 0; e < NE; e++) { p[e] = expf(lg[e] - m); s += p[e]; }
        float inv = 1.0f / s;
#pragma unroll
        for (int e = 0; e < NE; e++) p[e] *= inv;
        i1 = 0;
#pragma unroll
        for (int e = 1; e < NE; e++) if (p[e] > p[i1]) i1 = e;
        i2 = (i1 == 0) ? 1 : 0;
#pragma unroll
        for (int e = 0; e < NE; e++) if (e != i1 && p[e] > p[i2]) i2 = e;

        p1 = atomicAdd(&g_cnt[i1], 1);
        g_list[i1][p1] = t;
        g_wt[i1][p1]   = p[i1];
        p2 = atomicAdd(&g_cnt[i2], 1);
        g_list[i2][p2] = t;
        g_wt[i2][p2]   = p[i2];
    }
    i1 = __shfl_sync(0xffffffffu, i1, 0);
    i2 = __shfl_sync(0xffffffffu, i2, 0);
    p1 = __shfl_sync(0xffffffffu, p1, 0);
    p2 = __shfl_sync(0xffffffffu, p2, 0);

    __half* r1 = g_a2 + ((size_t)i1 * TOK + p1) * HID;
    __half* r2 = g_a2 + ((size_t)i2 * TOK + p2) * HID;
#pragma unroll
    for (int i = 0; i < 4; i++) {
        int c = i * 32 + lane;
        uint2 hv = make_uint2(pack_h2(xs4[i].x, xs4[i].y), pack_h2(xs4[i].z, xs4[i].w));
        *(uint2*)(r1 + c * 4) = hv;
        *(uint2*)(r2 + c * 4) = hv;
    }
}

// ---------------- kernel 4: weight transpose -> fp16 [N][K] (128k x 32n tiles) ----------------
template <int K, int N>
__device__ __forceinline__ void conv_w_body(const float* __restrict__ W,
                                            __half* __restrict__ oh) {
    __shared__ __half st[32][136];
    const int e  = blockIdx.z;
    const int n0 = blockIdx.x * 32;
    const int k0 = blockIdx.y * 128;
    const float* Wp = W + (size_t)e * K * N + (size_t)k0 * N + n0;

#pragma unroll
    for (int i = 0; i < 4; i++) {
        int idx = threadIdx.x + i * 256;
        int row = idx >> 3;
        int c4  = idx & 7;
        float4 v = *(const float4*)(Wp + (size_t)row * N + c4 * 4);
        int n = c4 * 4;
        st[n + 0][row] = __float2half_rn(v.x);
        st[n + 1][row] = __float2half_rn(v.y);
        st[n + 2][row] = __float2half_rn(v.z);
        st[n + 3][row] = __float2half_rn(v.w);
    }
    __syncthreads();

    __half* op = oh + (size_t)e * N * K + (size_t)n0 * K + k0;
#pragma unroll
    for (int i = 0; i < 8; i++) {
        int idx = threadIdx.x + i * 256;
        int n = idx >> 6;
        int j = idx & 63;
        *(uint32_t*)(op + (size_t)n * K + j * 2) = *(uint32_t*)&st[n][j * 2];
    }
}
__global__ void __launch_bounds__(256) conv_w1_kernel(const float* __restrict__ W) {
    conv_w_body<HID, FF>(W, g_w1);
}
__global__ void __launch_bounds__(256) conv_w2_kernel(const float* __restrict__ W) {
    conv_w_body<FF, HID>(W, g_w2);
}

// ---------------- HMMA mainloop: 128x128 CTA tile, K-tile 64, single fp16 pass ----------------
template <int KLEN, int STRIDE>
__device__ __forceinline__ void mma_loop(
    const __half* __restrict__ A, const __half* __restrict__ B,
    uint32_t sm, float acc[2][8][4])
{
    const uint32_t smA = sm;
    const uint32_t smB = sm + 49152;

    const int tid  = threadIdx.x;
    const int w    = tid >> 5, lane = tid & 31;
    const int wm   = (w & 3) * 32, wn = (w >> 2) * 64;
    const int lr   = tid >> 1;
    const int lc   = (tid & 1) * 4;
    const int lrow = lane & 15;
    const int lkof = (lane >> 4) * 8;

    uint32_t st_off[4];
#pragma unroll
    for (int i = 0; i < 4; i++) st_off[i] = SWZ(lr * 128 + (lc + i) * 16);

    constexpr int nT = KLEN / 64;
    const size_t lbase = (size_t)lr * STRIDE + lc * 8;

#pragma unroll
    for (int s = 0; s < 2; s++) {
        const __half* ap = A + lbase + s * 64;
        const __half* bp = B + lbase + s * 64;
        uint32_t ab = smA + s * 16384, bb = smB + s * 16384;
#pragma unroll
        for (int i = 0; i < 4; i++) {
            cp16(ab + st_off[i], ap + i * 8);
            cp16(bb + st_off[i], bp + i * 8);
        }
        asm volatile("cp.async.commit_group;" ::: "memory");
    }

    int buf = 0, buf2 = 2;
    for (int t = 0; t < nT; t++) {
        asm volatile("cp.async.wait_group 1;" ::: "memory");
        __syncthreads();

        int tn = t + 2;
        if (tn < nT) {
            const __half* ap = A + lbase + tn * 64;
            const __half* bp = B + lbase + tn * 64;
            uint32_t ab = smA + buf2 * 16384, bb = smB + buf2 * 16384;
#pragma unroll
            for (int i = 0; i < 4; i++) {
                cp16(ab + st_off[i], ap + i * 8);
                cp16(bb + st_off[i], bp + i * 8);
            }
        }
        asm volatile("cp.async.commit_group;" ::: "memory");

        uint32_t ab = smA + buf * 16384, bb = smB + buf * 16384;
#pragma unroll
        for (int kk = 0; kk < 4; kk++) {
            const int kb = (kk * 16 + lkof) * 2;
            uint32_t a0[4], a1[4], B0[4], B1[4], B2[4], B3[4];
            ldsm_x4(a0[0], a0[1], a0[2], a0[3], ab + SWZ((wm + lrow) * 128 + kb));
            ldsm_x4(a1[0], a1[1], a1[2], a1[3], ab + SWZ((wm + 16 + lrow) * 128 + kb));
            ldsm_x4(B0[0], B0[1], B0[2], B0[3], bb + SWZ((wn + lrow) * 128 + kb));
            ldsm_x4(B1[0], B1[1], B1[2], B1[3], bb + SWZ((wn + 16 + lrow) * 128 + kb));
            ldsm_x4(B2[0], B2[1], B2[2], B2[3], bb + SWZ((wn + 32 + lrow) * 128 + kb));
            ldsm_x4(B3[0], B3[1], B3[2], B3[3], bb + SWZ((wn + 48 + lrow) * 128 + kb));

            mma16816(acc[0][0], a0, B0[0], B0[2]);
            mma16816(acc[1][0], a1, B0[0], B0[2]);
            mma16816(acc[0][1], a0, B0[1], B0[3]);
            mma16816(acc[1][1], a1, B0[1], B0[3]);
            mma16816(acc[0][2], a0, B1[0], B1[2]);
            mma16816(acc[1][2], a1, B1[0], B1[2]);
            mma16816(acc[0][3], a0, B1[1], B1[3]);
            mma16816(acc[1][3], a1, B1[1], B1[3]);
            mma16816(acc[0][4], a0, B2[0], B2[2]);
            mma16816(acc[1][4], a1, B2[0], B2[2]);
            mma16816(acc[0][5], a0, B2[1], B2[3]);
            mma16816(acc[1][5], a1, B2[1], B2[3]);
            mma16816(acc[0][6], a0, B3[0], B3[2]);
            mma16816(acc[1][6], a1, B3[0], B3[2]);
            mma16816(acc[0][7], a0, B3[1], B3[3]);
            mma16816(acc[1][7], a1, B3[1], B3[3]);
        }
        buf  = (buf == 2) ? 0 : buf + 1;
        buf2 = (buf2 == 2) ? 0 : buf2 + 1;
    }
}

#define SMEM_DYN 98304

// ---------------- kernel 5: grouped GEMM1  h = gelu(x @ W1[e] + b1[e]) ----------------
__global__ void __launch_bounds__(256, 2)
gemm1_mma(const float* __restrict__ b1) {
    const int e   = blockIdx.z;
    const int cnt = g_cnt[e];
    const int m0  = blockIdx.y * 128;
    if (m0 >= cnt) return;
    const int n0  = blockIdx.x * 128;
    const size_t row0 = (size_t)e * TOK + m0;

    extern __shared__ char dynsm[];
    uint32_t sm = smem_u32(dynsm);

    float acc[2][8][4];
#pragma unroll
    for (int i = 0; i < 2; i++)
#pragma unroll
        for (int j = 0; j < 8; j++)
#pragma unroll
            for (int q = 0; q < 4; q++) acc[i][j][q] = 0.0f;

    mma_loop<HID, HID>(g_a2 + row0 * HID,
                       g_w1 + ((size_t)e * FF + n0) * HID,
                       sm, acc);

    const int w = threadIdx.x >> 5, lane = threadIdx.x & 31;
    const int wm = (w & 3) * 32, wn = (w >> 2) * 64;
    const float* bias = b1 + (size_t)e * FF + n0;
#pragma unroll
    for (int mi = 0; mi < 2; mi++) {
#pragma unroll
        for (int half = 0; half < 2; half++) {
            int rl = wm + mi * 16 + (lane >> 2) + half * 8;
            size_t hb = (row0 + rl) * FF + n0;
#pragma unroll
            for (int j = 0; j < 8; j++) {
                int c = wn + j * 8 + (lane & 3) * 2;
                float d0 = acc[mi][j][half * 2 + 0] + bias[c];
                float d1 = acc[mi][j][half * 2 + 1] + bias[c + 1];
                *(uint32_t*)(g_h + hb + c) = pack_h2(gelu_f(d0), gelu_f(d1));
            }
        }
    }
}

// ---------------- kernel 6: grouped GEMM2  out += wgt*(h @ W2[e] + b2[e]) ----------------
__global__ void __launch_bounds__(256, 2)
gemm2_mma(const float* __restrict__ b2, float* __restrict__ out) {
    const int e   = blockIdx.z;
    const int cnt = g_cnt[e];
    const int m0  = blockIdx.y * 128;
    if (m0 >= cnt) return;
    const int n0  = blockIdx.x * 128;
    const size_t row0 = (size_t)e * TOK + m0;

    extern __shared__ char dynsm[];
    uint32_t sm = smem_u32(dynsm);

    float acc[2][8][4];
#pragma unroll
    for (int i = 0; i < 2; i++)
#pragma unroll
        for (int j = 0; j < 8; j++)
#pragma unroll
            for (int q = 0; q < 4; q++) acc[i][j][q] = 0.0f;

    mma_loop<FF, FF>(g_h + row0 * FF,
                     g_w2 + ((size_t)e * HID + n0) * FF,
                     sm, acc);

    const int w = threadIdx.x >> 5, lane = threadIdx.x & 31;
    const int wm = (w & 3) * 32, wn = (w >> 2) * 64;
    const float* bias = b2 + (size_t)e * HID + n0;
#pragma unroll
    for (int mi = 0; mi < 2; mi++) {
#pragma unroll
        for (int half = 0; half < 2; half++) {
            int m = m0 + wm + mi * 16 + (lane >> 2) + half * 8;
            if (m >= cnt) continue;
            int token = g_list[e][m];
            float wgt = g_wt[e][m];
            float* orow = out + (size_t)token * HID + n0;
#pragma unroll
            for (int j = 0; j < 8; j++) {
                int c = wn + j * 8 + (lane & 3) * 2;
                red2(orow + c,
                     wgt * (acc[mi][j][half * 2 + 0] + bias[c]),
                     wgt * (acc[mi][j][half * 2 + 1] + bias[c + 1]));
            }
        }
    }
}

// ---------------- host launcher ----------------
extern "C" void kernel_launch(void* const* d_in, const int* in_sizes, int n_in,
                              void* d_out, int out_size) {
    const float* x  = (const float*)d_in[0];
    const float* Wg = (const float*)d_in[1];
    const float* bg = (const float*)d_in[2];
    const float* W1 = (const float*)d_in[3];
    const float* b1 = (const float*)d_in[4];
    const float* W2 = (const float*)d_in[5];
    const float* b2 = (const float*)d_in[6];
    float* out = (float*)d_out;

    cudaFuncSetAttribute(gemm1_mma, cudaFuncAttributeMaxDynamicSharedMemorySize, SMEM_DYN);
    cudaFuncSetAttribute(gemm2_mma, cudaFuncAttributeMaxDynamicSharedMemorySize, SMEM_DYN);

    cudaMemsetAsync(out, 0, (size_t)out_size * sizeof(float));
    zero_cnt_kernel<<<1, 32>>>();
    gate_kernel<<<TOK / 8, 256>>>(x, Wg, bg);
    conv_w1_kernel<<<dim3(FF / 32, HID / 128, NE), 256>>>(W1);
    conv_w2_kernel<<<dim3(HID / 32, FF / 128, NE), 256>>>(W2);
    gemm1_mma<<<dim3(FF / 128, TOK / 128, NE), 256, SMEM_DYN>>>(b1);
    gemm2_mma<<<dim3(HID / 128, TOK / 128, NE), 256, SMEM_DYN>>>(b2, out);
}

// round 13
// speedup vs baseline: 1.0761x; 1.0099x over previous
#include <cuda_runtime.h>
#include <cuda_fp16.h>
#include <cstdint>
#include <math.h>

#define TOK 16384
#define HID 512
#define FF  2048
#define NE  8

typedef unsigned long long u64;

// ---------------- device scratch (no allocations allowed) ----------------
__device__ int   g_cnt[NE];
__device__ int   g_list[NE][TOK];
__device__ float g_wt[NE][TOK];

__device__ __half g_a2[(size_t)NE * TOK * HID];  // per-expert gathered A rows (fp16)
__device__ __half g_h[(size_t)NE * TOK * FF];    // per-expert intermediate (fp16)
__device__ __half g_w1[(size_t)NE * FF * HID];   // [e][n(FF)][k(HID)]
__device__ __half g_w2[(size_t)NE * HID * FF];   // [e][n(HID)][k(FF)]

// ---------------- helpers ----------------
__device__ __forceinline__ uint32_t smem_u32(const void* p) {
    uint32_t a;
    asm("{ .reg .u64 t; cvta.to.shared.u64 t, %1; cvt.u32.u64 %0, t; }" : "=r"(a) : "l"(p));
    return a;
}
#define SWZ(x) ((x) ^ (((x) >> 3) & 0x70))

__device__ __forceinline__ void cp16(uint32_t dst, const void* src) {
    asm volatile("cp.async.cg.shared.global [%0], [%1], 16;" :: "r"(dst), "l"(src));
}
__device__ __forceinline__ void ldsm_x4(uint32_t& r0, uint32_t& r1, uint32_t& r2, uint32_t& r3,
                                        uint32_t addr) {
    asm volatile("ldmatrix.sync.aligned.m8n8.x4.shared.b16 {%0,%1,%2,%3}, [%4];"
                 : "=r"(r0), "=r"(r1), "=r"(r2), "=r"(r3) : "r"(addr));
}
__device__ __forceinline__ void mma16816(float* d, const uint32_t* a, uint32_t b0, uint32_t b1) {
    asm volatile("mma.sync.aligned.m16n8k16.row.col.f32.f16.f16.f32 "
                 "{%0,%1,%2,%3},{%4,%5,%6,%7},{%8,%9},{%0,%1,%2,%3};"
                 : "+f"(d[0]), "+f"(d[1]), "+f"(d[2]), "+f"(d[3])
                 : "r"(a[0]), "r"(a[1]), "r"(a[2]), "r"(a[3]), "r"(b0), "r"(b1));
}
__device__ __forceinline__ void red2(float* addr, float a, float b) {
    asm volatile("red.global.add.v2.f32 [%0], {%1, %2};" :: "l"(addr), "f"(a), "f"(b) : "memory");
}
__device__ __forceinline__ float gelu_f(float v) {
    float u = 1.5957691216057308f * (v + 0.044715f * v * v * v);
    return v / (1.0f + __expf(-u));
}
__device__ __forceinline__ uint32_t pack_h2(float a, float b) {
    __half ah = __float2half_rn(a);
    __half bh = __float2half_rn(b);
    return (uint32_t)__half_as_ushort(ah) | ((uint32_t)__half_as_ushort(bh) << 16);
}

// ---------------- fused prep: gate (blocks 0..2047), conv_w1 (2048..4095), conv_w2 (4096..6143)
__device__ __forceinline__ void gate_body(const float* __restrict__ x,
                                          const float* __restrict__ Wg,
                                          const float* __restrict__ bg,
                                          int blk) {
    int t = blk * 8 + (threadIdx.x >> 5);
    int lane = threadIdx.x & 31;
    const float4* xr4 = (const float4*)(x + (size_t)t * HID);

    float4 xs4[4];
    float acc[NE];
#pragma unroll
    for (int e = 0; e < NE; e++) acc[e] = 0.0f;

#pragma unroll
    for (int i = 0; i < 4; i++) {
        int c = i * 32 + lane;
        float4 xv = xr4[c];
        xs4[i] = xv;
        float xs[4] = {xv.x, xv.y, xv.z, xv.w};
        const float4* wg = (const float4*)(Wg + (size_t)(c * 4) * NE);
#pragma unroll
        for (int q = 0; q < 4; q++) {
            float4 w0 = wg[q * 2];
            float4 w1 = wg[q * 2 + 1];
            acc[0] += xs[q] * w0.x; acc[1] += xs[q] * w0.y;
            acc[2] += xs[q] * w0.z; acc[3] += xs[q] * w0.w;
            acc[4] += xs[q] * w1.x; acc[5] += xs[q] * w1.y;
            acc[6] += xs[q] * w1.z; acc[7] += xs[q] * w1.w;
        }
    }
#pragma unroll
    for (int off = 16; off > 0; off >>= 1) {
#pragma unroll
        for (int e = 0; e < NE; e++)
            acc[e] += __shfl_down_sync(0xffffffffu, acc[e], off);
    }

    int i1 = 0, i2 = 0, p1 = 0, p2 = 0;
    if (lane == 0) {
        float lg[NE], p[NE];
        float m = -1e30f;
#pragma unroll
        for (int e = 0; e < NE; e++) { lg[e] = acc[e] + bg[e]; m = fmaxf(m, lg[e]); }
        float s = 0.0f;
#pragma unroll
        for (int e = 0; e < NE; e++) { p[e] = expf(lg[e] - m); s += p[e]; }
        float inv = 1.0f / s;
#pragma unroll
        for (int e = 0; e < NE; e++) p[e] *= inv;
        i1 = 0;
#pragma unroll
        for (int e = 1; e < NE; e++) if (p[e] > p[i1]) i1 = e;
        i2 = (i1 == 0) ? 1 : 0;
#pragma unroll
        for (int e = 0; e < NE; e++) if (e != i1 && p[e] > p[i2]) i2 = e;

        p1 = atomicAdd(&g_cnt[i1], 1);
        g_list[i1][p1] = t;
        g_wt[i1][p1]   = p[i1];
        p2 = atomicAdd(&g_cnt[i2], 1);
        g_list[i2][p2] = t;
        g_wt[i2][p2]   = p[i2];
    }
    i1 = __shfl_sync(0xffffffffu, i1, 0);
    i2 = __shfl_sync(0xffffffffu, i2, 0);
    p1 = __shfl_sync(0xffffffffu, p1, 0);
    p2 = __shfl_sync(0xffffffffu, p2, 0);

    __half* r1 = g_a2 + ((size_t)i1 * TOK + p1) * HID;
    __half* r2 = g_a2 + ((size_t)i2 * TOK + p2) * HID;
#pragma unroll
    for (int i = 0; i < 4; i++) {
        int c = i * 32 + lane;
        uint2 hv = make_uint2(pack_h2(xs4[i].x, xs4[i].y), pack_h2(xs4[i].z, xs4[i].w));
        *(uint2*)(r1 + c * 4) = hv;
        *(uint2*)(r2 + c * 4) = hv;
    }
}

template <int K, int N>
__device__ __forceinline__ void conv_w_body(const float* __restrict__ W,
                                            __half* __restrict__ oh,
                                            __half st[32][136],
                                            int e, int n0, int k0) {
    const float* Wp = W + (size_t)e * K * N + (size_t)k0 * N + n0;
#pragma unroll
    for (int i = 0; i < 4; i++) {
        int idx = threadIdx.x + i * 256;
        int row = idx >> 3;
        int c4  = idx & 7;
        float4 v = *(const float4*)(Wp + (size_t)row * N + c4 * 4);
        int n = c4 * 4;
        st[n + 0][row] = __float2half_rn(v.x);
        st[n + 1][row] = __float2half_rn(v.y);
        st[n + 2][row] = __float2half_rn(v.z);
        st[n + 3][row] = __float2half_rn(v.w);
    }
    __syncthreads();
    __half* op = oh + (size_t)e * N * K + (size_t)n0 * K + k0;
#pragma unroll
    for (int i = 0; i < 8; i++) {
        int idx = threadIdx.x + i * 256;
        int n = idx >> 6;
        int j = idx & 63;
        *(uint32_t*)(op + (size_t)n * K + j * 2) = *(uint32_t*)&st[n][j * 2];
    }
}

__global__ void __launch_bounds__(256)
prep_kernel(const float* __restrict__ x,
            const float* __restrict__ Wg,
            const float* __restrict__ bg,
            const float* __restrict__ W1,
            const float* __restrict__ W2) {
    __shared__ __half st[32][136];
    int b = blockIdx.x;
    if (b < 2048) {
        gate_body(x, Wg, bg, b);
    } else if (b < 4096) {
        int idx = b - 2048;                  // conv_w1: grid was (64, 4, 8)
        int n0 = (idx & 63) * 32;
        int k0 = ((idx >> 6) & 3) * 128;
        int e  = idx >> 8;
        conv_w_body<HID, FF>(W1, g_w1, st, e, n0, k0);
    } else {
        int idx = b - 4096;                  // conv_w2: grid was (16, 16, 8)
        int n0 = (idx & 15) * 32;
        int k0 = ((idx >> 4) & 15) * 128;
        int e  = idx >> 8;
        conv_w_body<FF, HID>(W2, g_w2, st, e, n0, k0);
    }
}

// ---------------- HMMA mainloop: 128x128 CTA tile, K-tile 64, single fp16 pass ----------------
template <int KLEN, int STRIDE>
__device__ __forceinline__ void mma_loop(
    const __half* __restrict__ A, const __half* __restrict__ B,
    uint32_t sm, float acc[2][8][4])
{
    const uint32_t smA = sm;
    const uint32_t smB = sm + 49152;

    const int tid  = threadIdx.x;
    const int w    = tid >> 5, lane = tid & 31;
    const int wm   = (w & 3) * 32, wn = (w >> 2) * 64;
    const int lr   = tid >> 1;
    const int lc   = (tid & 1) * 4;
    const int lrow = lane & 15;
    const int lkof = (lane >> 4) * 8;

    uint32_t st_off[4];
#pragma unroll
    for (int i = 0; i < 4; i++) st_off[i] = SWZ(lr * 128 + (lc + i) * 16);

    constexpr int nT = KLEN / 64;
    const size_t lbase = (size_t)lr * STRIDE + lc * 8;

#pragma unroll
    for (int s = 0; s < 2; s++) {
        const __half* ap = A + lbase + s * 64;
        const __half* bp = B + lbase + s * 64;
        uint32_t ab = smA + s * 16384, bb = smB + s * 16384;
#pragma unroll
        for (int i = 0; i < 4; i++) {
            cp16(ab + st_off[i], ap + i * 8);
            cp16(bb + st_off[i], bp + i * 8);
        }
        asm volatile("cp.async.commit_group;" ::: "memory");
    }

    int buf = 0, buf2 = 2;
    for (int t = 0; t < nT; t++) {
        asm volatile("cp.async.wait_group 1;" ::: "memory");
        __syncthreads();

        int tn = t + 2;
        if (tn < nT) {
            const __half* ap = A + lbase + tn * 64;
            const __half* bp = B + lbase + tn * 64;
            uint32_t ab = smA + buf2 * 16384, bb = smB + buf2 * 16384;
#pragma unroll
            for (int i = 0; i < 4; i++) {
                cp16(ab + st_off[i], ap + i * 8);
                cp16(bb + st_off[i], bp + i * 8);
            }
        }
        asm volatile("cp.async.commit_group;" ::: "memory");

        uint32_t ab = smA + buf * 16384, bb = smB + buf * 16384;
#pragma unroll
        for (int kk = 0; kk < 4; kk++) {
            const int kb = (kk * 16 + lkof) * 2;
            uint32_t a0[4], a1[4], B0[4], B1[4], B2[4], B3[4];
            ldsm_x4(a0[0], a0[1], a0[2], a0[3], ab + SWZ((wm + lrow) * 128 + kb));
            ldsm_x4(a1[0], a1[1], a1[2], a1[3], ab + SWZ((wm + 16 + lrow) * 128 + kb));
            ldsm_x4(B0[0], B0[1], B0[2], B0[3], bb + SWZ((wn + lrow) * 128 + kb));
            ldsm_x4(B1[0], B1[1], B1[2], B1[3], bb + SWZ((wn + 16 + lrow) * 128 + kb));
            ldsm_x4(B2[0], B2[1], B2[2], B2[3], bb + SWZ((wn + 32 + lrow) * 128 + kb));
            ldsm_x4(B3[0], B3[1], B3[2], B3[3], bb + SWZ((wn + 48 + lrow) * 128 + kb));

            mma16816(acc[0][0], a0, B0[0], B0[2]);
            mma16816(acc[1][0], a1, B0[0], B0[2]);
            mma16816(acc[0][1], a0, B0[1], B0[3]);
            mma16816(acc[1][1], a1, B0[1], B0[3]);
            mma16816(acc[0][2], a0, B1[0], B1[2]);
            mma16816(acc[1][2], a1, B1[0], B1[2]);
            mma16816(acc[0][3], a0, B1[1], B1[3]);
            mma16816(acc[1][3], a1, B1[1], B1[3]);
            mma16816(acc[0][4], a0, B2[0], B2[2]);
            mma16816(acc[1][4], a1, B2[0], B2[2]);
            mma16816(acc[0][5], a0, B2[1], B2[3]);
            mma16816(acc[1][5], a1, B2[1], B2[3]);
            mma16816(acc[0][6], a0, B3[0], B3[2]);
            mma16816(acc[1][6], a1, B3[0], B3[2]);
            mma16816(acc[0][7], a0, B3[1], B3[3]);
            mma16816(acc[1][7], a1, B3[1], B3[3]);
        }
        buf  = (buf == 2) ? 0 : buf + 1;
        buf2 = (buf2 == 2) ? 0 : buf2 + 1;
    }
}

#define SMEM_DYN 98304

// ---------------- grouped GEMM1  h = gelu(x @ W1[e] + b1[e]) ----------------
__global__ void __launch_bounds__(256, 2)
gemm1_mma(const float* __restrict__ b1) {
    const int e   = blockIdx.z;
    const int cnt = g_cnt[e];
    const int m0  = blockIdx.y * 128;
    if (m0 >= cnt) return;
    const int n0  = blockIdx.x * 128;
    const size_t row0 = (size_t)e * TOK + m0;

    extern __shared__ char dynsm[];
    uint32_t sm = smem_u32(dynsm);

    float acc[2][8][4];
#pragma unroll
    for (int i = 0; i < 2; i++)
#pragma unroll
        for (int j = 0; j < 8; j++)
#pragma unroll
            for (int q = 0; q < 4; q++) acc[i][j][q] = 0.0f;

    mma_loop<HID, HID>(g_a2 + row0 * HID,
                       g_w1 + ((size_t)e * FF + n0) * HID,
                       sm, acc);

    const int w = threadIdx.x >> 5, lane = threadIdx.x & 31;
    const int wm = (w & 3) * 32, wn = (w >> 2) * 64;
    const float* bias = b1 + (size_t)e * FF + n0;
#pragma unroll
    for (int mi = 0; mi < 2; mi++) {
#pragma unroll
        for (int half = 0; half < 2; half++) {
            int rl = wm + mi * 16 + (lane >> 2) + half * 8;
            size_t hb = (row0 + rl) * FF + n0;
#pragma unroll
            for (int j = 0; j < 8; j++) {
                int c = wn + j * 8 + (lane & 3) * 2;
                float d0 = acc[mi][j][half * 2 + 0] + bias[c];
                float d1 = acc[mi][j][half * 2 + 1] + bias[c + 1];
                *(uint32_t*)(g_h + hb + c) = pack_h2(gelu_f(d0), gelu_f(d1));
            }
        }
    }
}

// ---------------- grouped GEMM2  out += wgt*(h @ W2[e] + b2[e]) ----------------
__global__ void __launch_bounds__(256, 2)
gemm2_mma(const float* __restrict__ b2, float* __restrict__ out) {
    const int e   = blockIdx.z;
    const int cnt = g_cnt[e];
    const int m0  = blockIdx.y * 128;
    if (m0 >= cnt) return;
    const int n0  = blockIdx.x * 128;
    const size_t row0 = (size_t)e * TOK + m0;

    extern __shared__ char dynsm[];
    uint32_t sm = smem_u32(dynsm);

    float acc[2][8][4];
#pragma unroll
    for (int i = 0; i < 2; i++)
#pragma unroll
        for (int j = 0; j < 8; j++)
#pragma unroll
            for (int q = 0; q < 4; q++) acc[i][j][q] = 0.0f;

    mma_loop<FF, FF>(g_h + row0 * FF,
                     g_w2 + ((size_t)e * HID + n0) * FF,
                     sm, acc);

    const int w = threadIdx.x >> 5, lane = threadIdx.x & 31;
    const int wm = (w & 3) * 32, wn = (w >> 2) * 64;
    const float* bias = b2 + (size_t)e * HID + n0;
#pragma unroll
    for (int mi = 0; mi < 2; mi++) {
#pragma unroll
        for (int half = 0; half < 2; half++) {
            int m = m0 + wm + mi * 16 + (lane >> 2) + half * 8;
            if (m >= cnt) continue;
            int token = g_list[e][m];
            float wgt = g_wt[e][m];
            float* orow = out + (size_t)token * HID + n0;
#pragma unroll
            for (int j = 0; j < 8; j++) {
                int c = wn + j * 8 + (lane & 3) * 2;
                red2(orow + c,
                     wgt * (acc[mi][j][half * 2 + 0] + bias[c]),
                     wgt * (acc[mi][j][half * 2 + 1] + bias[c + 1]));
            }
        }
    }
}

// ---------------- host launcher ----------------
extern "C" void kernel_launch(void* const* d_in, const int* in_sizes, int n_in,
                              void* d_out, int out_size) {
    const float* x  = (const float*)d_in[0];
    const float* Wg = (const float*)d_in[1];
    const float* bg = (const float*)d_in[2];
    const float* W1 = (const float*)d_in[3];
    const float* b1 = (const float*)d_in[4];
    const float* W2 = (const float*)d_in[5];
    const float* b2 = (const float*)d_in[6];
    float* out = (float*)d_out;

    cudaFuncSetAttribute(gemm1_mma, cudaFuncAttributeMaxDynamicSharedMemorySize, SMEM_DYN);
    cudaFuncSetAttribute(gemm2_mma, cudaFuncAttributeMaxDynamicSharedMemorySize, SMEM_DYN);

    void* cnt_ptr = nullptr;
    cudaGetSymbolAddress(&cnt_ptr, g_cnt);

    cudaMemsetAsync(out, 0, (size_t)out_size * sizeof(float));
    cudaMemsetAsync(cnt_ptr, 0, NE * sizeof(int));
    prep_kernel<<<6144, 256>>>(x, Wg, bg, W1, W2);
    gemm1_mma<<<dim3(FF / 128, TOK / 128, NE), 256, SMEM_DYN>>>(b1);
    gemm2_mma<<<dim3(HID / 128, TOK / 128, NE), 256, SMEM_DYN>>>(b2, out);
}